// round 15
// baseline (speedup 1.0000x reference)
#include <cuda_runtime.h>
#include <cuda_bf16.h>

#define C_DIM   10000
#define B_DIM   8192
#define M_SCALE 4.0f
#define THREADS 256
#define N4      (C_DIM / 4)               // 2500 float4 per row
#define FULL_IT (N4 / THREADS)            // 9
#define TAIL_N  (N4 - FULL_IT * THREADS)  // 196

// Per-row loss scratch + completion counter (reset by reduce kernel each run).
__device__ float        g_row_loss[B_DIM];
__device__ unsigned int g_done = 0u;

// ---------------- Kernel 1: per-row loss (early PDL trigger, REDG finish) ---
__global__ __launch_bounds__(THREADS) void ems_row_kernel(
    const float* __restrict__ inputs,
    const int* __restrict__ targets)   // int32 (JAX default int width)
{
    const int row = blockIdx.x;
    const int tid = threadIdx.x;
    const float4* __restrict__ rowp =
        reinterpret_cast<const float4*>(inputs + (size_t)row * C_DIM);

    // Front-batched loads: 9 full + predicated tail (MLP ~10) — proven fastest.
    float4 v[FULL_IT];
    #pragma unroll
    for (int k = 0; k < FULL_IT; k++)
        v[k] = __ldg(&rowp[tid + k * THREADS]);

    const bool has_tail = (tid < TAIL_N);
    float4 vt = has_tail ? __ldg(&rowp[FULL_IT * THREADS + tid])
                         : make_float4(0.f, 0.f, 0.f, 0.f);

    // EARLY PDL trigger: dependent grid launches now and waits on the data
    // flag; data ordering is handled by red.release below, not by PDL.
    asm volatile("griddepcontrol.launch_dependents;");

    float s = 0.0f;
    #pragma unroll
    for (int k = 0; k < FULL_IT; k++) {
        s += __expf(v[k].x);
        s += __expf(v[k].y);
        s += __expf(v[k].z);
        s += __expf(v[k].w);
    }
    if (has_tail) {
        s += __expf(vt.x);
        s += __expf(vt.y);
        s += __expf(vt.z);
        s += __expf(vt.w);
    }

    // ---- block reduction ----
    #pragma unroll
    for (int off = 16; off > 0; off >>= 1)
        s += __shfl_xor_sync(0xFFFFFFFFu, s, off);

    __shared__ float warp_sums[THREADS / 32];
    const int lane = tid & 31, wid = tid >> 5;
    if (lane == 0) warp_sums[wid] = s;
    __syncthreads();

    if (wid == 0) {
        float t = (lane < THREADS / 32) ? warp_sums[lane] : 0.0f;
        #pragma unroll
        for (int off = 4; off > 0; off >>= 1)
            t += __shfl_xor_sync(0xFFFFFFFFu, t, off);
        if (lane == 0) {
            const int tgt = targets[row];
            const float xt  = __ldg(inputs + (size_t)row * C_DIM + tgt);
            const float xtm = M_SCALE * xt;
            // replace exp(x_t) by exp(4*x_t) in the row sum
            const float sp = t - __expf(xt) + __expf(xtm);
            g_row_loss[row] = __logf(sp) - xtm;   // plain STG
            // Fence-free completion: release-REDG orders the STG above and
            // does not stall this CTA (no return value, no MEMBAR drain).
            asm volatile("red.release.gpu.global.add.u32 [%0], %1;"
                         :: "l"(&g_done), "r"(1u) : "memory");
        }
    }
}

// ---------------- Kernel 2: mean of 8192 floats (PDL + flag-poll) -----------
__global__ __launch_bounds__(THREADS) void ems_reduce_kernel(float* __restrict__ out)
{
    // Enter as soon as the primary's CTAs have triggered (early in their life).
    asm volatile("griddepcontrol.wait;" ::: "memory");

    const int tid = threadIdx.x;
    const int lane = tid & 31, wid = tid >> 5;
    __shared__ float warp_sums[THREADS / 32];

    // Poll the completion counter with acquire semantics.
    if (tid == 0) {
        unsigned int c;
        do {
            asm volatile("ld.acquire.gpu.global.u32 %0, [%1];"
                         : "=r"(c) : "l"(&g_done));
        } while (c != (unsigned)B_DIM);
    }
    __syncthreads();

    const float4* __restrict__ p = reinterpret_cast<const float4*>(g_row_loss);
    float4 v[8];   // 2048 float4 total; 8 per thread, front-batched (L2-resident)
    #pragma unroll
    for (int k = 0; k < 8; k++)
        v[k] = p[tid + k * THREADS];

    float s = 0.0f;
    #pragma unroll
    for (int k = 0; k < 8; k++)
        s += (v[k].x + v[k].y) + (v[k].z + v[k].w);

    #pragma unroll
    for (int off = 16; off > 0; off >>= 1)
        s += __shfl_xor_sync(0xFFFFFFFFu, s, off);

    if (lane == 0) warp_sums[wid] = s;
    __syncthreads();

    if (wid == 0) {
        float t = (lane < THREADS / 32) ? warp_sums[lane] : 0.0f;
        #pragma unroll
        for (int off = 4; off > 0; off >>= 1)
            t += __shfl_xor_sync(0xFFFFFFFFu, t, off);
        if (lane == 0) {
            out[0] = t * (1.0f / (float)B_DIM);
            g_done = 0u;   // reset for next graph replay (visible at kernel end)
        }
    }
}

extern "C" void kernel_launch(void* const* d_in, const int* in_sizes, int n_in,
                              void* d_out, int out_size)
{
    const float* inputs = (const float*)d_in[0];
    const int* targets = (const int*)d_in[1];
    float* out = (float*)d_out;

    ems_row_kernel<<<B_DIM, THREADS>>>(inputs, targets);

    // Secondary launch with Programmatic Stream Serialization: launch overhead
    // and rampup overlap the primary; data ordering via the release counter.
    cudaLaunchConfig_t cfg = {};
    cfg.gridDim  = dim3(1, 1, 1);
    cfg.blockDim = dim3(THREADS, 1, 1);
    cfg.dynamicSmemBytes = 0;
    cfg.stream = 0;  // same (legacy default) stream the harness captures
    cudaLaunchAttribute attr[1];
    attr[0].id = cudaLaunchAttributeProgrammaticStreamSerialization;
    attr[0].val.programmaticStreamSerializationAllowed = 1;
    cfg.attrs = attr;
    cfg.numAttrs = 1;
    cudaLaunchKernelEx(&cfg, ems_reduce_kernel, out);
}

// round 16
// speedup vs baseline: 1.0423x; 1.0423x over previous
#include <cuda_runtime.h>
#include <cuda_bf16.h>

#define C_DIM   10000
#define B_DIM   8192
#define M_SCALE 4.0f
#define THREADS 256
#define N4      (C_DIM / 4)               // 2500 float4 per row
#define FULL_IT (N4 / THREADS)            // 9
#define TAIL_N  (N4 - FULL_IT * THREADS)  // 196
#define NCTA    1184                      // 148 SMs x 8 CTAs

// Scratch (reset by the last CTA each run; zero-init valid for first run).
__device__ float        g_row_loss[B_DIM];
__device__ unsigned int g_ticket = 0u;
__device__ unsigned int g_done   = 0u;

__global__ __launch_bounds__(THREADS) void ems_persist_kernel(
    const float* __restrict__ inputs,
    const int* __restrict__ targets,   // int32 (JAX default int width)
    float* __restrict__ out)
{
    const int tid  = threadIdx.x;
    const int lane = tid & 31, wid = tid >> 5;

    __shared__ float        warp_sums[THREADS / 32];
    __shared__ unsigned int s_row[2];
    __shared__ unsigned int s_last;

    // Grab first ticket.
    if (tid == 0) s_row[0] = atomicAdd(&g_ticket, 1u);
    __syncthreads();

    int par = 0;
    for (;;) {
        const unsigned int row = s_row[par];
        // Prefetch next ticket; its latency hides under this row's work.
        // (visibility to other threads guaranteed by the reduction syncthreads)
        if (tid == 0) s_row[par ^ 1] = atomicAdd(&g_ticket, 1u);
        if (row >= (unsigned)B_DIM) break;
        par ^= 1;

        const float4* __restrict__ rowp =
            reinterpret_cast<const float4*>(inputs + (size_t)row * C_DIM);

        // ---- proven R9 body: front-batched loads (MLP ~10) ----
        float4 v[FULL_IT];
        #pragma unroll
        for (int k = 0; k < FULL_IT; k++)
            v[k] = __ldg(&rowp[tid + k * THREADS]);

        const bool has_tail = (tid < TAIL_N);
        float4 vt = has_tail ? __ldg(&rowp[FULL_IT * THREADS + tid])
                             : make_float4(0.f, 0.f, 0.f, 0.f);

        float s = 0.0f;
        #pragma unroll
        for (int k = 0; k < FULL_IT; k++) {
            s += __expf(v[k].x);
            s += __expf(v[k].y);
            s += __expf(v[k].z);
            s += __expf(v[k].w);
        }
        if (has_tail) {
            s += __expf(vt.x);
            s += __expf(vt.y);
            s += __expf(vt.z);
            s += __expf(vt.w);
        }

        // ---- block reduction ----
        #pragma unroll
        for (int off = 16; off > 0; off >>= 1)
            s += __shfl_xor_sync(0xFFFFFFFFu, s, off);
        if (lane == 0) warp_sums[wid] = s;
        __syncthreads();

        if (wid == 0) {
            float t = (lane < THREADS / 32) ? warp_sums[lane] : 0.0f;
            #pragma unroll
            for (int off = 4; off > 0; off >>= 1)
                t += __shfl_xor_sync(0xFFFFFFFFu, t, off);
            if (lane == 0) {
                const int tgt = targets[row];
                const float xt  = __ldg(inputs + (size_t)row * C_DIM + tgt);
                const float xtm = M_SCALE * xt;
                // replace exp(x_t) by exp(4*x_t) in the row sum
                const float sp = t - __expf(xt) + __expf(xtm);
                g_row_loss[row] = __logf(sp) - xtm;   // plain STG, no fence
            }
        }
        __syncthreads();   // separates warp_sums/s_row reuse across rows
    }

    // ---- per-CTA completion: ONE fence + ONE counter atomic per CTA ----
    __syncthreads();
    if (tid == 0) {
        __threadfence();   // release all this CTA's row-loss stores
        s_last = (atomicAdd(&g_done, 1u) == (unsigned)(NCTA - 1));
    }
    __syncthreads();

    // ---- last CTA: final mean over all 8192 losses (L2-resident) ----
    if (s_last) {
        __threadfence();   // acquire side
        const float4* __restrict__ p = reinterpret_cast<const float4*>(g_row_loss);
        float4 w[8];       // 2048 float4; 8 per thread, front-batched
        #pragma unroll
        for (int k = 0; k < 8; k++)
            w[k] = p[tid + k * THREADS];

        float r = 0.0f;
        #pragma unroll
        for (int k = 0; k < 8; k++)
            r += (w[k].x + w[k].y) + (w[k].z + w[k].w);

        #pragma unroll
        for (int off = 16; off > 0; off >>= 1)
            r += __shfl_xor_sync(0xFFFFFFFFu, r, off);
        if (lane == 0) warp_sums[wid] = r;
        __syncthreads();

        if (wid == 0) {
            float t = (lane < THREADS / 32) ? warp_sums[lane] : 0.0f;
            #pragma unroll
            for (int off = 4; off > 0; off >>= 1)
                t += __shfl_xor_sync(0xFFFFFFFFu, t, off);
            if (lane == 0) {
                out[0] = t * (1.0f / (float)B_DIM);
                // Reset counters for the next graph replay (stream-ordered).
                g_done   = 0u;
                g_ticket = 0u;
            }
        }
    }
}

extern "C" void kernel_launch(void* const* d_in, const int* in_sizes, int n_in,
                              void* d_out, int out_size)
{
    const float* inputs = (const float*)d_in[0];
    const int* targets = (const int*)d_in[1];
    float* out = (float*)d_out;

    ems_persist_kernel<<<NCTA, THREADS>>>(inputs, targets, out);
}